// round 7
// baseline (speedup 1.0000x reference)
#include <cuda_runtime.h>
#include <cuda_bf16.h>
#include <cstdint>

#define RTYPES 8
#define CSZ 128
#define MCAP 10000
#define ECAP 100000
#define PCAP (ECAP + (RTYPES + 1) * CSZ)
#define NBMAX ((ECAP + CSZ - 1) / CSZ + RTYPES)
#define CHUNK_BYTES 163840   // AdHi 32K | AdLo 32K | AsHi 48K | AsLo 48K

// ---------------- device scratch (no runtime alloc allowed) ----------------
__device__ float g_num[MCAP*128];
__device__ float g_denom[MCAP*8];
__device__ int   g_perm[PCAP];
__device__ int   g_counts[RTYPES];
__device__ int   g_cursor[RTYPES];
// Pre-swizzled bf16 hi/lo weight images (K-major SW-style blocked atoms)
__device__ __align__(128) unsigned char g_Bq[RTYPES*2*32768];
__device__ __align__(128) unsigned char g_Bk[RTYPES*2*49152];
__device__ __align__(128) unsigned char g_Bv[RTYPES*2*49152];
// Per-chunk LN'd A-tile images (written by k_ln, staged by k_edge)
__device__ __align__(128) unsigned char g_A[(size_t)NBMAX * CHUNK_BYTES];

// ---------------- SMEM byte layout for k_edge ----------------
#define OFF_AD_HI 0          // 32768 (later: Bk_lo/Bv_lo stage, then bounce)
#define OFF_AD_LO 32768
#define OFF_AS_HI 65536      // 49152
#define OFF_AS_LO 114688
#define OFF_B     163840     // 49152 B stage
#define OFF_EX    212992     // float[128*8]
#define OFF_DST   217088     // int[128]
#define SMEM_EDGE 217664

typedef unsigned char uchar;

__device__ __forceinline__ float warp_sum(float v) {
#pragma unroll
  for (int o = 16; o; o >>= 1) v += __shfl_xor_sync(0xffffffffu, v, o);
  return v;
}

// blocked-atom K-major byte offset: atom = 8 rows x 64 bf16 (1024B),
// 16 m-atoms, k-atoms stride 16KB; xor swizzle for conflict-free ldsm.
__device__ __forceinline__ uint32_t koff(int m, int k) {
  uint32_t off = (uint32_t)(((m >> 3) + (k >> 6) * 16) * 1024 + (m & 7) * 128 + (k & 63) * 2);
  return off ^ ((off >> 3) & 0x70);
}
__device__ __forceinline__ uint32_t koff2(uint32_t rowbase, int k) {
  uint32_t off = rowbase + ((k >> 6) << 14) + ((k & 63) << 1);
  return off ^ ((off >> 3) & 0x70);
}

__device__ __forceinline__ void cp16(uint32_t dst, const void* src) {
  asm volatile("cp.async.cg.shared.global [%0], [%1], 16;" :: "r"(dst), "l"(src));
}
#define CP_COMMIT() asm volatile("cp.async.commit_group;")
#define CP_WAIT0()  asm volatile("cp.async.wait_group 0;")
#define CP_WAIT1()  asm volatile("cp.async.wait_group 1;")

__device__ __forceinline__ void ldsm4(uint32_t* r, uint32_t a) {
  asm volatile("ldmatrix.sync.aligned.m8n8.x4.shared.b16 {%0,%1,%2,%3}, [%4];"
    : "=r"(r[0]), "=r"(r[1]), "=r"(r[2]), "=r"(r[3]) : "r"(a));
}
__device__ __forceinline__ void mma16816(float* c, const uint32_t* a, const uint32_t* b) {
  asm volatile("mma.sync.aligned.m16n8k16.row.col.f32.bf16.bf16.f32 "
    "{%0,%1,%2,%3}, {%4,%5,%6,%7}, {%8,%9}, {%0,%1,%2,%3};"
    : "+f"(c[0]), "+f"(c[1]), "+f"(c[2]), "+f"(c[3])
    : "r"(a[0]), "r"(a[1]), "r"(a[2]), "r"(a[3]), "r"(b[0]), "r"(b[1]));
}
__device__ __forceinline__ void red4(float* p, float4 v) {
  asm volatile("red.global.add.v4.f32 [%0], {%1,%2,%3,%4};"
    :: "l"(p), "f"(v.x), "f"(v.y), "f"(v.z), "f"(v.w) : "memory");
}

// One pass: C[32 x NT*16] += A[32xK] @ B[.xK]^T for one warp tile.
template<int NK, int NT>
__device__ __forceinline__ void gemm_pass(
    uint32_t aB, uint32_t bB, int m0, int nb0, int lane,
    float (&acc)[2][2*NT][4])
{
  const int r0 = m0 + (lane & 15);
  const int r1 = r0 + 16;
  const uint32_t arb0 = (uint32_t)(((r0 >> 3) << 10) + ((r0 & 7) << 7));
  const uint32_t arb1 = (uint32_t)(((r1 >> 3) << 10) + ((r1 & 7) << 7));
  const int ak = (lane >> 4) << 3;
  const int bn = nb0 + (lane & 7) + ((lane >> 4) << 3);
  const int bk = ((lane >> 3) & 1) << 3;
  uint32_t brb[NT];
#pragma unroll
  for (int p = 0; p < NT; ++p) {
    int n = bn + p * 16;
    brb[p] = (uint32_t)(((n >> 3) << 10) + ((n & 7) << 7));
  }
#pragma unroll
  for (int ks = 0; ks < NK; ++ks) {
    const int k0 = ks << 4;
    uint32_t A0[4], A1[4], B[NT][4];
    ldsm4(A0, aB + koff2(arb0, k0 + ak));
    ldsm4(A1, aB + koff2(arb1, k0 + ak));
#pragma unroll
    for (int p = 0; p < NT; ++p) ldsm4(B[p], bB + koff2(brb[p], k0 + bk));
#pragma unroll
    for (int p = 0; p < NT; ++p) {
      mma16816(acc[0][2*p],   A0, &B[p][0]);
      mma16816(acc[0][2*p+1], A0, &B[p][2]);
      mma16816(acc[1][2*p],   A1, &B[p][0]);
      mma16816(acc[1][2*p+1], A1, &B[p][2]);
    }
  }
}

// ================= fused init + count + weight-image prep =================
__global__ void __launch_bounds__(256) k_prep(
    const int* __restrict__ etype, int E, int M,
    const float* __restrict__ Wq, const float* __restrict__ Wk,
    const float* __restrict__ Wv, int NBI)
{
  __shared__ int loc[RTYPES];
  const int bid = blockIdx.x, tid = threadIdx.x;
  if (bid < NBI) {
    int i = bid * 256 + tid;
    if (i < M*128) g_num[i] = 0.f;
    if (i < M*8)   g_denom[i] = 0.f;
    if (i < PCAP)  g_perm[i] = -1;
    if (i < RTYPES) { g_counts[i] = 0; g_cursor[i] = 0; }
    return;
  }
  if (bid < NBI + 128) {
    if (tid < RTYPES) loc[tid] = 0;
    __syncthreads();
    for (int i = (bid - NBI)*256 + tid; i < E; i += 128*256)
      atomicAdd(&loc[etype[i]], 1);
    __syncthreads();
    if (tid < RTYPES && loc[tid]) atomicAdd(&g_counts[tid], loc[tid]);
    return;
  }
  int idx = (bid - NBI - 128) * 256 + tid;
  float val; uchar* hbase; uint32_t off; int half_stride;
  if (idx < 131072) {
    int r = idx >> 14, rem = idx & 16383, k = rem >> 7, n = rem & 127;
    val = Wq[r*16384 + k*128 + n];
    hbase = g_Bq + r*65536; half_stride = 32768; off = koff(n, k);
  } else if (idx < 131072 + 196608) {
    int i2 = idx - 131072;
    int r = i2 / 24576, rem = i2 % 24576, k = rem >> 7, n = rem & 127;
    val = (k < 160) ? Wk[r*20480 + k*128 + n] : 0.f;
    hbase = g_Bk + r*98304; half_stride = 49152; off = koff(n, k);
  } else {
    int i3 = idx - 131072 - 196608;
    if (i3 >= 196608) return;
    int r = i3 / 24576, rem = i3 % 24576, k = rem >> 7, n = rem & 127;
    val = (k < 160) ? Wv[r*20480 + k*128 + n] : 0.f;
    hbase = g_Bv + r*98304; half_stride = 49152; off = koff(n, k);
  }
  __nv_bfloat16 hi = __float2bfloat16(val);
  __nv_bfloat16 lo = __float2bfloat16(val - __bfloat162float(hi));
  *(__nv_bfloat16*)(hbase + off) = hi;
  *(__nv_bfloat16*)(hbase + half_stride + off) = lo;
}

// ================= scatter (with inline prefix scan) =================
__global__ void k_scatter(const int* __restrict__ etype, int E) {
  __shared__ int loc[RTYPES], base[RTYPES], pf[RTYPES];
  const int t = threadIdx.x;
  if (t < RTYPES) loc[t] = 0;
  __syncthreads();
  const int start = blockIdx.x * 1024;
  const int end = min(start + 1024, E);
  for (int i = start + t; i < end; i += 256) atomicAdd(&loc[etype[i]], 1);
  if (t == 0) {
    int b = 0;
    for (int r = 0; r < RTYPES; ++r) {
      pf[r] = b;
      b += ((g_counts[r] + CSZ - 1) / CSZ) * CSZ;
    }
  }
  __syncthreads();
  if (t < RTYPES) {
    base[t] = pf[t] + (loc[t] ? atomicAdd(&g_cursor[t], loc[t]) : 0);
    loc[t] = 0;
  }
  __syncthreads();
  for (int i = start + t; i < end; i += 256) {
    int r = etype[i];
    g_perm[base[r] + atomicAdd(&loc[r], 1)] = i;
  }
}

// ================= LN kernel: one warp per edge slot, writes A images =====
__global__ void __launch_bounds__(256) k_ln(
    const float* __restrict__ src_h, const float* __restrict__ src_tw,
    const float* __restrict__ src_tb, const float* __restrict__ edge_h,
    const float* __restrict__ date, const int* __restrict__ src_idx,
    const int* __restrict__ dst_idx,
    const float* __restrict__ sg, const float* __restrict__ sb,
    const float* __restrict__ dg, const float* __restrict__ db)
{
  const int slot = blockIdx.x * 8 + (threadIdx.x >> 5);
  const int lane = threadIdx.x & 31;
  const int chunk = slot >> 7, c = slot & 127;
  uchar* base = g_A + (size_t)chunk * CHUNK_BYTES;
  const int e = g_perm[slot];

  if (e < 0) {   // pad slot: zero the row in all four images
    const unsigned short z = 0;
#pragma unroll
    for (int kk = 0; kk < 4; ++kk) {
      uint32_t o = koff(c, lane + 32*kk);
      *(unsigned short*)(base + o) = z;
      *(unsigned short*)(base + 32768 + o) = z;
    }
#pragma unroll
    for (int kk = 0; kk < 6; ++kk) {   // 160 data cols + 32 pad cols
      uint32_t o = koff(c, lane + 32*kk);
      *(unsigned short*)(base + 65536 + o) = z;
      *(unsigned short*)(base + 114688 + o) = z;
    }
    return;
  }

  const float t = date[e];
  const int s = src_idx[e];
  const int d = dst_idx[e];

  // dst side (128 dims)
  float xd[4];
#pragma unroll
  for (int kk = 0; kk < 4; ++kk) xd[kk] = src_h[d*128 + lane + 32*kk];
  xd[0] *= __sinf(src_tw[d*32+lane]*t + src_tb[d*32+lane]);
  float mu = warp_sum(xd[0]+xd[1]+xd[2]+xd[3]) * (1.f/128.f);
  float vv = 0.f;
#pragma unroll
  for (int kk = 0; kk < 4; ++kk) { float dl = xd[kk]-mu; vv = fmaf(dl,dl,vv); }
  float rs = rsqrtf(warp_sum(vv)*(1.f/128.f) + 1e-5f);
#pragma unroll
  for (int kk = 0; kk < 4; ++kk) {
    int i = lane + 32*kk;
    float v = (xd[kk]-mu)*rs*dg[i] + db[i];
    __nv_bfloat16 hi = __float2bfloat16(v);
    __nv_bfloat16 lo = __float2bfloat16(v - __bfloat162float(hi));
    uint32_t o = koff(c, i);
    *(__nv_bfloat16*)(base + o) = hi;
    *(__nv_bfloat16*)(base + 32768 + o) = lo;
  }

  // src side (160 dims)
  float xs[5];
#pragma unroll
  for (int kk = 0; kk < 4; ++kk) xs[kk] = src_h[s*128 + lane + 32*kk];
  xs[0] *= __sinf(src_tw[s*32+lane]*t + src_tb[s*32+lane]);
  xs[4] = edge_h[e*32 + lane];
  mu = warp_sum(xs[0]+xs[1]+xs[2]+xs[3]+xs[4]) * (1.f/160.f);
  vv = 0.f;
#pragma unroll
  for (int kk = 0; kk < 5; ++kk) { float dl = xs[kk]-mu; vv = fmaf(dl,dl,vv); }
  rs = rsqrtf(warp_sum(vv)*(1.f/160.f) + 1e-5f);
#pragma unroll
  for (int kk = 0; kk < 5; ++kk) {
    int i = lane + 32*kk;
    float v = (xs[kk]-mu)*rs*sg[i] + sb[i];
    __nv_bfloat16 hi = __float2bfloat16(v);
    __nv_bfloat16 lo = __float2bfloat16(v - __bfloat162float(hi));
    uint32_t o = koff(c, i);
    *(__nv_bfloat16*)(base + 65536 + o) = hi;
    *(__nv_bfloat16*)(base + 114688 + o) = lo;
  }
  {  // K-pad [160,192)
    uint32_t o = koff(c, 160 + lane);
    *(unsigned short*)(base + 65536 + o) = 0;
    *(unsigned short*)(base + 114688 + o) = 0;
  }
}

// ================= main edge kernel: lean GEMM + epilogue =================
__global__ void __launch_bounds__(512, 1) k_edge(
    const int* __restrict__ etype)
{
  extern __shared__ __align__(1024) char sm[];
  float* sEx  = (float*)(sm + OFF_EX);
  int*   sDst = (int*)(sm + OFF_DST);
  const uint32_t smb = (uint32_t)__cvta_generic_to_shared(sm);

  const int tid = threadIdx.x, wid = tid >> 5, lane = tid & 31;
  const int chunk = blockIdx.x;

  const int e0 = g_perm[chunk * CSZ];
  if (e0 < 0) return;           // pure-padding chunk
  const int et = etype[e0];

  // ---- G1: A_d (64KB) + Bq_hi (32KB); G2: A_s (96KB) ----
  {
    const uchar* ab = g_A + (size_t)chunk * CHUNK_BYTES;
    for (int o = tid*16; o < 65536; o += 8192) cp16(smb + o, ab + o);
    const uchar* bq = g_Bq + et*65536;
    for (int o = tid*16; o < 32768; o += 8192) cp16(smb + OFF_B + o, bq + o);
    CP_COMMIT();
    for (int o = tid*16; o < 98304; o += 8192) cp16(smb + 65536 + o, ab + 65536 + o);
    CP_COMMIT();
  }
  if (tid < CSZ) {
    int e = g_perm[chunk*CSZ + tid];
    sDst[tid] = (e >= 0) ? __ldg(&((const int*)0 == 0 ? (const int*)0 : (const int*)0)[0]) * 0 : -1;  // placeholder (replaced below)
  }
  __syncthreads();
  CP_WAIT1();      // G1 done (A_d + Bq_hi)
  __syncthreads();

  const int m0 = (wid >> 2) * 32;
  const int n0 = (wid & 3) * 32;
  const uint32_t aDhi = smb + OFF_AD_HI, aDlo = smb + OFF_AD_LO;
  const uint32_t aShi = smb + OFF_AS_HI, aSlo = smb + OFF_AS_LO;
  const uint32_t bS = smb + OFF_B, bA = smb;   // bA = A_d region reused for B-lo

  // ---- q GEMM: passes 1-2 (Bq_hi), restage Bq_lo, pass 3 ----
  float accQ[2][4][4];
#pragma unroll
  for (int a = 0; a < 2; ++a)
#pragma unroll
    for (int b = 0; b < 4; ++b)
#pragma unroll
      for (int cc = 0; cc < 4; ++cc) accQ[a][b][cc] = 0.f;
  gemm_pass<8,2>(aDhi, bS, m0, n0, lane, accQ);
  gemm_pass<8,2>(aDlo, bS, m0, n0, lane, accQ);
  __syncthreads();
  { const uchar* bq = g_Bq + et*65536 + 32768;
    for (int o = tid*16; o < 32768; o += 8192) cp16(bS - smb + smb + OFF_B + o - OFF_B + OFF_B + o*0, bq + o); }
  CP_COMMIT(); CP_WAIT0(); __syncthreads();
  gemm_pass<8,2>(aDhi, bS, m0, n0, lane, accQ);
  __syncthreads();

  // ---- stage Bk hi->B1, lo->A_d region (one wait) ----
  { const uchar* bk = g_Bk + et*98304;
    for (int o = tid*16; o < 49152; o += 8192) cp16(smb + OFF_B + o, bk + o);
    for (int o = tid*16; o < 49152; o += 8192) cp16(smb + o, bk + 49152 + o); }
  CP_COMMIT(); CP_WAIT0(); __syncthreads();

  // ---- k GEMM in two 16-col halves with incremental per-head dots ----
  const float scl = 0.0883883476483184f;  // 1/sqrt(128)
#pragma unroll
  for (int h = 0; h < 2; ++h) {
    float accC[2][2][4];
#pragma unroll
    for (int a = 0; a < 2; ++a)
#pragma unroll
      for (int b = 0; b < 2; ++b)
#pragma unroll
        for (int cc = 0; cc < 4; ++cc) accC[a][b][cc] = 0.f;
    gemm_pass<10,1>(aShi, bS, m0, n0 + h*16, lane, accC);
    gemm_pass<10,1>(aSlo, bS, m0, n0 + h*16, lane, accC);
    gemm_pass<10,1>(aShi, bA, m0, n0 + h*16, lane, accC);
    const int head = (n0 >> 4) + h;
#pragma unroll
    for (int mi = 0; mi < 2; ++mi)
#pragma unroll
      for (int rh = 0; rh < 2; ++rh) {
        float p = 0.f;
#pragma unroll
        for (int nj = 0; nj < 2; ++nj) {
          p = fmaf(accQ[mi][2*h+nj][2*rh],   accC[mi][nj][2*rh],   p);
          p = fmaf(accQ[mi][2*h+nj][2*rh+1], accC[mi][nj][2*rh+1], p);
        }
        p += __shfl_xor_sync(0xffffffffu, p, 1);
        p += __shfl_xor_sync(0xffffffffu, p, 2);
        if ((lane & 3) == 0) {
          int row = m0 + mi*16 + rh*8 + (lane >> 2);
          float ex = __expf(p * scl);
          sEx[row*8 + head] = ex;
          int d = sDst[row];
          if (d >= 0) atomicAdd(&g_denom[d*8 + head], ex);
        }
      }
  }
  __syncthreads();

  // ---- stage Bv hi->B1, lo->A_d (one wait) ----
  { const uchar* bv = g_Bv + et*98304;
    for (int o = tid*16; o < 49152; o += 8192) cp16(smb + OFF_B + o, bv + o);
    for (int o = tid*16; o < 49152; o += 8192) cp16(smb + o, bv + 49152 + o); }
  CP_COMMIT(); CP_WAIT0(); __syncthreads();

  // ---- v GEMM (3 passes, full 32-col tile) ----
  float accV[2][4][4];
#pragma unroll
  for (int a = 0; a < 2; ++a)
#pragma unroll
    for (int b = 0; b < 4; ++b)
#pragma unroll
      for (int cc = 0; cc < 4; ++cc) accV[a][b][cc] = 0.f;
  gemm_pass<10,2>(aShi, bS, m0, n0, lane, accV);
  gemm_pass<10,2>(aSlo, bS, m0, n0, lane, accV);
  gemm_pass<10,2>(aShi, bA, m0, n0, lane, accV);
  __syncthreads();   // all reads of A_d region done -> reuse as bounce

  // ---- epilogue: scale by ex -> xor-swizzled bounce -> red.v4 scatter ----
  {
    float* bounce = (float*)sm;   // 128x128 fp32, physical col = col ^ ((row&7)<<2)
#pragma unroll
    for (int mi = 0; mi < 2; ++mi)
#pragma unroll
      for (int nj = 0; nj < 4; ++nj) {
        int col = n0 + nj*8 + (lane & 3)*2;
        int head = (n0 >> 4) + (nj >> 1);
        int row0 = m0 + mi*16 + (lane >> 2);
        int row1 = row0 + 8;
        float ex0 = sEx[row0*8 + head], ex1 = sEx[row1*8 + head];
        *(float2*)&bounce[row0*128 + (col ^ ((row0 & 7) << 2))] =
            make_float2(accV[mi][nj][0]*ex0, accV[mi][nj][1]*ex0);
        *(float2*)&bounce[row1*128 + (col ^ ((row1 & 7) << 2))] =
            make_float2(accV[mi][nj][2]*ex1, accV[mi][nj][3]*ex1);
      }
  }
  __syncthreads();
  {
    const float* bounce = (const float*)sm;
#pragma unroll
    for (int i = 0; i < 8; ++i) {
      int e = wid*8 + i;
      int d = sDst[e];
      if (d < 0) continue;
      int col = (lane*4) ^ ((e & 7) << 2);
      float4 v = *(const float4*)&bounce[e*128 + col];
      // physical slot col holds logical cols (col^s)=lane*4 .. +3
      red4(&g_num[d*128 + (lane*4)], v);
    }
  }
}

// ================= output kernel =================
__global__ void __launch_bounds__(128) k_out(
    const float* __restrict__ src_h, const int* __restrict__ ntype,
    const float* __restrict__ Wa, const float* __restrict__ h_bias,
    const float* __restrict__ skip, float* __restrict__ out, int M)
{
  extern __shared__ float smem[];
  float* sWa = smem;
  float* sh  = smem + 16384;
  const int tt  = blockIdx.y;
  const int tid = threadIdx.x;
  {
    const float4* srcw = (const float4*)(Wa + tt*16384);
    for (int idx = tid; idx < 4096; idx += 128) ((float4*)sWa)[idx] = srcw[idx];
  }
  const float gate = 1.f / (1.f + __expf(-skip[tt]));
  const float bias = h_bias[tt*128 + tid];
  __syncthreads();

  const int m1 = min((int)(blockIdx.x + 1) * 64, M);
  for (int m = blockIdx.x * 64; m < m1; ++m) {
    if (ntype[m] != tt) continue;
    float dden = g_denom[m*8 + (tid >> 4)];
    float hv = (dden > 0.f) ? g_num[m*128 + tid] / dden : 0.f;
    sh[tid] = hv + bias;
    __syncthreads();
    float a0 = 0.f, a1 = 0.f, a2 = 0.f, a3 = 0.f;
#pragma unroll
    for (int i = 0; i < 128; i += 4) {
      a0 = fmaf(sh[i+0], sWa[(i+0)*128 + tid], a0);
      a1 = fmaf(sh[i+1], sWa[(i+1)*128 + tid], a1);
      a2 = fmaf(sh[i+2], sWa[(i+2)*128 + tid], a2);
      a3 = fmaf(sh[i+3], sWa[(i+3)*128 + tid], a3);
    }
    out[m*128 + tid] = ((a0+a1)+(a2+a3))*gate + src_h[m*128 + tid]*(1.f - gate);
    __syncthreads();
  }
}

// fix-up kernel for sDst (kept out of k_edge's hot path): fills a small
// global per-chunk dst table is unnecessary — instead k_edge loads dst_idx
// directly. (See k_edge2 wrapper below.)
__global__ void __launch_bounds__(512, 1) k_edge_real(
    const int* __restrict__ etype, const int* __restrict__ dst_idx);

extern "C" void kernel_launch(void* const* d_in, const int* in_sizes, int n_in,
                              void* d_out, int out_size) {
  const float* src_h  = (const float*)d_in[0];
  const float* src_tw = (const float*)d_in[1];
  const float* src_tb = (const float*)d_in[2];
  const float* edge_h = (const float*)d_in[3];
  const float* date   = (const float*)d_in[4];
  const int*   src_idx= (const int*)d_in[5];
  const int*   dst_idx= (const int*)d_in[6];
  const int*   etype  = (const int*)d_in[7];
  const int*   ntype  = (const int*)d_in[8];
  const float* Wq     = (const float*)d_in[9];
  const float* Wk     = (const float*)d_in[10];
  const float* Wv     = (const float*)d_in[11];
  const float* Wa     = (const float*)d_in[12];
  const float* h_bias = (const float*)d_in[13];
  const float* skip   = (const float*)d_in[14];
  const float* sg     = (const float*)d_in[15];
  const float* sb     = (const float*)d_in[16];
  const float* dg     = (const float*)d_in[17];
  const float* db     = (const float*)d_in[18];
  float* out = (float*)d_out;

  const int E = in_sizes[4];
  const int M = in_sizes[8];
  const int T = in_sizes[14];
  const int NB = (E + CSZ - 1)/CSZ + RTYPES;

  cudaFuncSetAttribute(k_edge_real, cudaFuncAttributeMaxDynamicSharedMemorySize, SMEM_EDGE);
  cudaFuncSetAttribute(k_out, cudaFuncAttributeMaxDynamicSharedMemorySize, (16384+128)*4);

  int initN = M * 128; if (PCAP > initN) initN = PCAP;
  const int NBI = (initN + 255) / 256;
  const int NBP = (131072 + 196608 + 196608 + 255) / 256;
  k_prep<<<NBI + 128 + NBP, 256>>>(etype, E, M, Wq, Wk, Wv, NBI);
  k_scatter<<<(E + 1023)/1024, 256>>>(etype, E);
  k_ln<<<NB*16, 256>>>(src_h, src_tw, src_tb, edge_h, date, src_idx, dst_idx,
                       sg, sb, dg, db);
  k_edge_real<<<NB, 512, SMEM_EDGE>>>(etype, dst_idx);
  dim3 g3((M + 63)/64, T);
  k_out<<<g3, 128, (16384+128)*4>>>(src_h, ntype, Wa, h_bias, skip, out, M);
}

// Real k_edge definition (the earlier k_edge above is dead code kept minimal;
// this is the launched kernel). Identical to k_edge but with a correct sDst
// load from dst_idx.
__global__ void __launch_bounds__(512, 1) k_edge_real(
    const int* __restrict__ etype, const int* __restrict__ dst_idx)
{
  extern __shared__ __align__(1024) char sm[];
  float* sEx  = (float*)(sm + OFF_EX);
  int*   sDst = (int*)(sm + OFF_DST);
  const uint32_t smb = (uint32_t)__cvta_generic_to_shared(sm);

  const int tid = threadIdx.x, wid = tid >> 5, lane = tid & 31;
  const int chunk = blockIdx.x;

  const int e0 = g_perm[chunk * CSZ];
  if (e0 < 0) return;
  const int et = etype[e0];

  {
    const uchar* ab = g_A + (size_t)chunk * CHUNK_BYTES;
    for (int o = tid*16; o < 65536; o += 8192) cp16(smb + o, ab + o);
    const uchar* bq = g_Bq + et*65536;
    for (int o = tid*16; o < 32768; o += 8192) cp16(smb + OFF_B + o, bq + o);
    CP_COMMIT();
    for (int o = tid*16; o < 98304; o += 8192) cp16(smb + 65536 + o, ab + 65536 + o);
    CP_COMMIT();
  }
  if (tid < CSZ) {
    int e = g_perm[chunk*CSZ + tid];
    sDst[tid] = (e >= 0) ? dst_idx[e] : -1;
  }
  CP_WAIT1();
  __syncthreads();

  const int m0 = (wid >> 2) * 32;
  const int n0 = (wid & 3) * 32;
  const uint32_t aDhi = smb + OFF_AD_HI, aDlo = smb + OFF_AD_LO;
  const uint32_t aShi = smb + OFF_AS_HI, aSlo = smb + OFF_AS_LO;
  const uint32_t bS = smb + OFF_B, bA = smb;

  float accQ[2][4][4];
#pragma unroll
  for (int a = 0; a < 2; ++a)
#pragma unroll
    for (int b = 0; b < 4; ++b)
#pragma unroll
      for (int cc = 0; cc < 4; ++cc) accQ[a][b][cc] = 0.f;
  gemm_pass<8,2>(aDhi, bS, m0, n0, lane, accQ);
  gemm_pass<8,2>(aDlo, bS, m0, n0, lane, accQ);
  __syncthreads();
  { const uchar* bq = g_Bq + et*65536 + 32768;
    for (int o = tid*16; o < 32768; o += 8192) cp16(smb + OFF_B + o, bq + o); }
  CP_COMMIT(); CP_WAIT0(); __syncthreads();
  gemm_pass<8,2>(aDhi, bS, m0, n0, lane, accQ);
  __syncthreads();

  { const uchar* bk = g_Bk + et*98304;
    for (int o = tid*16; o < 49152; o += 8192) cp16(smb + OFF_B + o, bk + o);
    for (int o = tid*16; o < 49152; o += 8192) cp16(smb + o, bk + 49152 + o); }
  CP_COMMIT(); CP_WAIT0(); __syncthreads();

  const float scl = 0.0883883476483184f;
#pragma unroll
  for (int h = 0; h < 2; ++h) {
    float accC[2][2][4];
#pragma unroll
    for (int a = 0; a < 2; ++a)
#pragma unroll
      for (int b = 0; b < 2; ++b)
#pragma unroll
        for (int cc = 0; cc < 4; ++cc) accC[a][b][cc] = 0.f;
    gemm_pass<10,1>(aShi, bS, m0, n0 + h*16, lane, accC);
    gemm_pass<10,1>(aSlo, bS, m0, n0 + h*16, lane, accC);
    gemm_pass<10,1>(aShi, bA, m0, n0 + h*16, lane, accC);
    const int head = (n0 >> 4) + h;
#pragma unroll
    for (int mi = 0; mi < 2; ++mi)
#pragma unroll
      for (int rh = 0; rh < 2; ++rh) {
        float p = 0.f;
#pragma unroll
        for (int nj = 0; nj < 2; ++nj) {
          p = fmaf(accQ[mi][2*h+nj][2*rh],   accC[mi][nj][2*rh],   p);
          p = fmaf(accQ[mi][2*h+nj][2*rh+1], accC[mi][nj][2*rh+1], p);
        }
        p += __shfl_xor_sync(0xffffffffu, p, 1);
        p += __shfl_xor_sync(0xffffffffu, p, 2);
        if ((lane & 3) == 0) {
          int row = m0 + mi*16 + rh*8 + (lane >> 2);
          float ex = __expf(p * scl);
          sEx[row*8 + head] = ex;
          int d = sDst[row];
          if (d >= 0) atomicAdd(&g_denom[d*8 + head], ex);
        }
      }
  }
  __syncthreads();

  { const uchar* bv = g_Bv + et*98304;
    for (int o = tid*16; o < 49152; o += 8192) cp16(smb + OFF_B + o, bv + o);
    for (int o = tid*16; o < 49152; o += 8192) cp16(smb + o, bv + 49152 + o); }
  CP_COMMIT(); CP_WAIT0(); __syncthreads();

  float accV[2][4][4];
#pragma unroll
  for (int a = 0; a < 2; ++a)
#pragma unroll
    for (int b = 0; b < 4; ++b)
#pragma unroll
      for (int cc = 0; cc < 4; ++cc) accV[a][b][cc] = 0.f;
  gemm_pass<10,2>(aShi, bS, m0, n0, lane, accV);
  gemm_pass<10,2>(aSlo, bS, m0, n0, lane, accV);
  gemm_pass<10,2>(aShi, bA, m0, n0, lane, accV);
  __syncthreads();

  {
    float* bounce = (float*)sm;
#pragma unroll
    for (int mi = 0; mi < 2; ++mi)
#pragma unroll
      for (int nj = 0; nj < 4; ++nj) {
        int col = n0 + nj*8 + (lane & 3)*2;
        int head = (n0 >> 4) + (nj >> 1);
        int row0 = m0 + mi*16 + (lane >> 2);
        int row1 = row0 + 8;
        float ex0 = sEx[row0*8 + head], ex1 = sEx[row1*8 + head];
        *(float2*)&bounce[row0*128 + (col ^ ((row0 & 7) << 2))] =
            make_float2(accV[mi][nj][0]*ex0, accV[mi][nj][1]*ex0);
        *(float2*)&bounce[row1*128 + (col ^ ((row1 & 7) << 2))] =
            make_float2(accV[mi][nj][2]*ex1, accV[mi][nj][3]*ex1);
      }
  }
  __syncthreads();
  {
    const float* bounce = (const float*)sm;
#pragma unroll
    for (int i = 0; i < 8; ++i) {
      int e = wid*8 + i;
      int d = sDst[e];
      if (d < 0) continue;
      int col = (lane*4) ^ ((e & 7) << 2);
      float4 v = *(const float4*)&bounce[e*128 + col];
      red4(&g_num[d*128 + (lane*4)], v);
    }
  }
}